// round 3
// baseline (speedup 1.0000x reference)
#include <cuda_runtime.h>
#include <cuda_fp16.h>
#include <cstdint>
#include <cstddef>

#define N_NODES 100000
#define R_REL   8
#define HF      128

// 8 * 100000 * 128 halves = 204.8 MB scratch for H[r][node][hto] (fp16)
__device__ __half g_Hh[(size_t)R_REL * N_NODES * HF];

// ---------------------------------------------------------------------------
__device__ __forceinline__ uint32_t f32_to_tf32(float f) {
    uint32_t o;
    asm("cvt.rna.tf32.f32 %0, %1;" : "=r"(o) : "f"(f));
    return o;
}

// ---------------------------------------------------------------------------
__global__ void zero_kernel(float4* out, int n4) {
    int i = blockIdx.x * blockDim.x + threadIdx.x;
    if (i < n4) out[i] = make_float4(0.f, 0.f, 0.f, 0.f);
}

// ---------------------------------------------------------------------------
// GEMM: H[r] = nodes @ W[r]^T  (tf32 mma.sync). Block tile 128x128.
// Warp tile 32 rows x 64 cols; A fragments held in registers across all 8
// relations (loaded from smem exactly once). B staged per relation.
// H stored as fp16.
// ---------------------------------------------------------------------------
#define LDA 132
#define LDB 132
#define GEMM_SMEM (2 * 128 * 132 * 4)

__global__ __launch_bounds__(256, 1) void rgcn_gemm(
    const float* __restrict__ nodes, const float* __restrict__ weights)
{
    extern __shared__ uint32_t smem[];
    uint32_t* As = smem;             // [128][LDA] tf32 bits (row m, col k)
    uint32_t* Bs = smem + 128 * LDA; // [128][LDB] tf32 bits, Bs[n][k]

    const int tid  = threadIdx.x;
    const int warp = tid >> 5;
    const int lane = tid & 31;
    const int g    = lane >> 2;   // groupID (0..7)
    const int tg   = lane & 3;    // thread-in-group (0..3)
    const int wm   = warp >> 1;   // warp m index (0..3) -> 32 rows
    const int wn   = warp & 1;    // warp n index (0..1) -> 64 cols
    const int m0   = blockIdx.x * 128;

    // ---- load A tile into smem (zero-pad rows >= N_NODES), tf32 convert ----
    {
        const float4* src = (const float4*)nodes;
        uint4* As4 = (uint4*)As;   // row stride = 33 uint4 (132 floats)
        #pragma unroll
        for (int i = tid; i < 128 * 32; i += 256) {
            int row = i >> 5, c4 = i & 31;
            float4 v = make_float4(0.f, 0.f, 0.f, 0.f);
            if (m0 + row < N_NODES) v = src[(size_t)(m0 + row) * 32 + c4];
            uint4 t;
            t.x = f32_to_tf32(v.x); t.y = f32_to_tf32(v.y);
            t.z = f32_to_tf32(v.z); t.w = f32_to_tf32(v.w);
            As4[row * 33 + c4] = t;
        }
    }
    __syncthreads();

    // ---- A fragments for this warp's 32 rows, all K, in registers ----
    uint32_t areg[2][16][4];
    #pragma unroll
    for (int ms = 0; ms < 2; ms++) {
        const int mrow = wm * 32 + ms * 16;
        #pragma unroll
        for (int kk = 0; kk < 16; kk++) {
            areg[ms][kk][0] = As[(mrow + g)     * LDA + kk * 8 + tg];
            areg[ms][kk][1] = As[(mrow + g + 8) * LDA + kk * 8 + tg];
            areg[ms][kk][2] = As[(mrow + g)     * LDA + kk * 8 + tg + 4];
            areg[ms][kk][3] = As[(mrow + g + 8) * LDA + kk * 8 + tg + 4];
        }
    }

    for (int r = 0; r < R_REL; r++) {
        __syncthreads();   // previous relation's B reads done
        // ---- stage W[r] into smem: Bs[n][k], tf32 ----
        {
            const float4* src = (const float4*)(weights + (size_t)r * HF * HF);
            uint4* Bs4 = (uint4*)Bs;
            #pragma unroll
            for (int i = tid; i < 128 * 32; i += 256) {
                int n = i >> 5, k4 = i & 31;
                float4 v = src[n * 32 + k4];
                uint4 t;
                t.x = f32_to_tf32(v.x); t.y = f32_to_tf32(v.y);
                t.z = f32_to_tf32(v.z); t.w = f32_to_tf32(v.w);
                Bs4[n * 33 + k4] = t;
            }
        }
        __syncthreads();

        float acc[2][8][4];
        #pragma unroll
        for (int ms = 0; ms < 2; ms++)
            #pragma unroll
            for (int nt = 0; nt < 8; nt++)
                #pragma unroll
                for (int q = 0; q < 4; q++) acc[ms][nt][q] = 0.f;

        #pragma unroll 4
        for (int kk = 0; kk < 16; kk++) {
            uint32_t b[8][2];
            #pragma unroll
            for (int nt = 0; nt < 8; nt++) {
                int n = wn * 64 + nt * 8 + g;
                b[nt][0] = Bs[n * LDB + kk * 8 + tg];
                b[nt][1] = Bs[n * LDB + kk * 8 + tg + 4];
            }
            #pragma unroll
            for (int ms = 0; ms < 2; ms++) {
                #pragma unroll
                for (int nt = 0; nt < 8; nt++) {
                    asm volatile(
                        "mma.sync.aligned.m16n8k8.row.col.f32.tf32.tf32.f32 "
                        "{%0,%1,%2,%3}, {%4,%5,%6,%7}, {%8,%9}, {%0,%1,%2,%3};"
                        : "+f"(acc[ms][nt][0]), "+f"(acc[ms][nt][1]),
                          "+f"(acc[ms][nt][2]), "+f"(acc[ms][nt][3])
                        : "r"(areg[ms][kk][0]), "r"(areg[ms][kk][1]),
                          "r"(areg[ms][kk][2]), "r"(areg[ms][kk][3]),
                          "r"(b[nt][0]), "r"(b[nt][1]));
                }
            }
        }

        __half* Hr = g_Hh + (size_t)r * N_NODES * HF;
        #pragma unroll
        for (int ms = 0; ms < 2; ms++) {
            const int row0 = m0 + wm * 32 + ms * 16 + g;
            const int row1 = row0 + 8;
            #pragma unroll
            for (int nt = 0; nt < 8; nt++) {
                int col = wn * 64 + nt * 8 + 2 * tg;
                if (row0 < N_NODES)
                    *(__half2*)&Hr[(size_t)row0 * HF + col] =
                        __floats2half2_rn(acc[ms][nt][0], acc[ms][nt][1]);
                if (row1 < N_NODES)
                    *(__half2*)&Hr[(size_t)row1 * HF + col] =
                        __floats2half2_rn(acc[ms][nt][2], acc[ms][nt][3]);
            }
        }
    }
}

// ---------------------------------------------------------------------------
// Edge scatter: 16 lanes per edge (2 edges per warp); lane l reads 8 halves
// (16B).  out[row % N] += value * H[row / N][col]
// ---------------------------------------------------------------------------
__global__ __launch_bounds__(256) void rgcn_scatter(
    const int*   __restrict__ rows,
    const int*   __restrict__ cols,
    const float* __restrict__ vals,
    float*       __restrict__ out,
    int nnz)
{
    int t = blockIdx.x * 256 + threadIdx.x;
    int e = t >> 4;
    int l = t & 15;
    if (e >= nnz) return;

    int row = __ldg(rows + e);
    int c   = __ldg(cols + e);
    float v = __ldg(vals + e);
    int r = row / N_NODES;
    int n = row - r * N_NODES;

    const uint4* src = (const uint4*)(g_Hh + ((size_t)r * N_NODES + c) * HF);
    uint4 p = __ldg(src + l);                 // 8 halves

    __half2* hp = (__half2*)&p;
    float2 f0 = __half22float2(hp[0]);
    float2 f1 = __half22float2(hp[1]);
    float2 f2 = __half22float2(hp[2]);
    float2 f3 = __half22float2(hp[3]);

    float* dst = out + (size_t)n * HF + l * 8;
    asm volatile("red.global.add.v4.f32 [%0], {%1,%2,%3,%4};"
                 :: "l"(dst), "f"(v * f0.x), "f"(v * f0.y),
                    "f"(v * f1.x), "f"(v * f1.y) : "memory");
    asm volatile("red.global.add.v4.f32 [%0], {%1,%2,%3,%4};"
                 :: "l"(dst + 4), "f"(v * f2.x), "f"(v * f2.y),
                    "f"(v * f3.x), "f"(v * f3.y) : "memory");
}

// ---------------------------------------------------------------------------
__global__ void relu_kernel(float4* out, int n4) {
    int i = blockIdx.x * blockDim.x + threadIdx.x;
    if (i < n4) {
        float4 v = out[i];
        v.x = fmaxf(v.x, 0.f); v.y = fmaxf(v.y, 0.f);
        v.z = fmaxf(v.z, 0.f); v.w = fmaxf(v.w, 0.f);
        out[i] = v;
    }
}

// ---------------------------------------------------------------------------
extern "C" void kernel_launch(void* const* d_in, const int* in_sizes, int n_in,
                              void* d_out, int out_size) {
    const float* nodes   = (const float*)d_in[0];
    const int*   indices = (const int*)d_in[1];   // int32 (jax x64 disabled)
    const float* vals    = (const float*)d_in[2];
    const float* weights = (const float*)d_in[3];
    float* out = (float*)d_out;

    const int nnz = in_sizes[2];            // 1,600,000
    const int n4  = N_NODES * HF / 4;       // 3,200,000 float4s in out

    zero_kernel<<<(n4 + 255) / 256, 256>>>((float4*)out, n4);

    cudaFuncSetAttribute(rgcn_gemm, cudaFuncAttributeMaxDynamicSharedMemorySize,
                         GEMM_SMEM);
    rgcn_gemm<<<(N_NODES + 127) / 128, 256, GEMM_SMEM>>>(nodes, weights);

    rgcn_scatter<<<((size_t)nnz * 16 + 255) / 256, 256>>>(
        indices, indices + nnz, vals, out, nnz);

    relu_kernel<<<(n4 + 255) / 256, 256>>>((float4*)out, n4);
}

// round 4
// speedup vs baseline: 1.5678x; 1.5678x over previous
#include <cuda_runtime.h>
#include <cuda_fp16.h>
#include <cstdint>
#include <cstddef>

#define N_NODES 100000
#define R_REL   8
#define HF      128

// 8 * 100000 * 128 halves = 204.8 MB scratch for H[r][node][hto] (fp16)
__device__ __half g_Hh[(size_t)R_REL * N_NODES * HF];

// ---------------------------------------------------------------------------
__device__ __forceinline__ uint32_t f32_to_tf32(float f) {
    uint32_t o;
    asm("cvt.rna.tf32.f32 %0, %1;" : "=r"(o) : "f"(f));
    return o;
}

// ---------------------------------------------------------------------------
__global__ void zero_kernel(float4* out, int n4) {
    int i = blockIdx.x * blockDim.x + threadIdx.x;
    if (i < n4) out[i] = make_float4(0.f, 0.f, 0.f, 0.f);
}

// ---------------------------------------------------------------------------
// GEMM: H[r] = nodes @ W[r]^T   (tf32 mma.sync, R2 structure: warp tile
// 128x16, B-fragments in registers per relation, A re-read from padded smem).
// H stored as fp16.
// ---------------------------------------------------------------------------
#define LDA 132
#define LDB 132
#define GEMM_SMEM (2 * 128 * 132 * 4)

__global__ __launch_bounds__(256, 1) void rgcn_gemm(
    const float* __restrict__ nodes, const float* __restrict__ weights)
{
    extern __shared__ uint32_t smem[];
    uint32_t* As = smem;             // [128][LDA]  tf32 bits (row m, col k)
    uint32_t* Bs = smem + 128 * LDA; // [128][LDB]  tf32 bits, Bs[n][k]

    const int tid  = threadIdx.x;
    const int warp = tid >> 5;
    const int lane = tid & 31;
    const int g    = lane >> 2;   // groupID
    const int tg   = lane & 3;    // thread-in-group
    const int m0   = blockIdx.x * 128;
    const int nbase = warp * 16;  // each warp owns 16 output columns

    // ---- load A tile (zero-pad rows >= N_NODES), convert to tf32 ----
    {
        const float4* src = (const float4*)nodes;
        uint4* As4 = (uint4*)As;   // row stride = 33 uint4 (132 floats)
        #pragma unroll
        for (int i = tid; i < 128 * 32; i += 256) {
            int row = i >> 5, c4 = i & 31;
            float4 v = make_float4(0.f, 0.f, 0.f, 0.f);
            if (m0 + row < N_NODES) v = src[(size_t)(m0 + row) * 32 + c4];
            uint4 t;
            t.x = f32_to_tf32(v.x); t.y = f32_to_tf32(v.y);
            t.z = f32_to_tf32(v.z); t.w = f32_to_tf32(v.w);
            As4[row * 33 + c4] = t;
        }
    }

    for (int r = 0; r < R_REL; r++) {
        __syncthreads();   // prev iter's B-reg loads done (and A fill on iter 0)
        // ---- stage W[r] into smem: Bs[n][k] ----
        {
            const float4* src = (const float4*)(weights + (size_t)r * HF * HF);
            uint4* Bs4 = (uint4*)Bs;
            #pragma unroll
            for (int i = tid; i < 128 * 32; i += 256) {
                int n = i >> 5, k4 = i & 31;
                float4 v = src[n * 32 + k4];
                uint4 t;
                t.x = f32_to_tf32(v.x); t.y = f32_to_tf32(v.y);
                t.z = f32_to_tf32(v.z); t.w = f32_to_tf32(v.w);
                Bs4[n * 33 + k4] = t;
            }
        }
        __syncthreads();

        // ---- B fragments for this warp's 16 columns, all K, held in regs ----
        uint32_t breg[16][2][2];
        #pragma unroll
        for (int kk = 0; kk < 16; kk++) {
            #pragma unroll
            for (int nt = 0; nt < 2; nt++) {
                int n = nbase + nt * 8 + g;
                int k = kk * 8 + tg;
                breg[kk][nt][0] = Bs[n * LDB + k];
                breg[kk][nt][1] = Bs[n * LDB + k + 4];
            }
        }

        __half* Hr = g_Hh + (size_t)r * N_NODES * HF;
        #pragma unroll 1
        for (int msub = 0; msub < 8; msub++) {
            float acc[2][4] = {};
            const int mrow = msub * 16;
            #pragma unroll
            for (int kk = 0; kk < 16; kk++) {
                uint32_t a0 = As[(mrow + g)     * LDA + kk * 8 + tg];
                uint32_t a1 = As[(mrow + g + 8) * LDA + kk * 8 + tg];
                uint32_t a2 = As[(mrow + g)     * LDA + kk * 8 + tg + 4];
                uint32_t a3 = As[(mrow + g + 8) * LDA + kk * 8 + tg + 4];
                #pragma unroll
                for (int nt = 0; nt < 2; nt++) {
                    asm volatile(
                        "mma.sync.aligned.m16n8k8.row.col.f32.tf32.tf32.f32 "
                        "{%0,%1,%2,%3}, {%4,%5,%6,%7}, {%8,%9}, {%0,%1,%2,%3};"
                        : "+f"(acc[nt][0]), "+f"(acc[nt][1]),
                          "+f"(acc[nt][2]), "+f"(acc[nt][3])
                        : "r"(a0), "r"(a1), "r"(a2), "r"(a3),
                          "r"(breg[kk][nt][0]), "r"(breg[kk][nt][1]));
                }
            }
            const int row0 = m0 + mrow + g;
            const int row1 = row0 + 8;
            #pragma unroll
            for (int nt = 0; nt < 2; nt++) {
                int col = nbase + nt * 8 + 2 * tg;
                if (row0 < N_NODES)
                    *(__half2*)&Hr[(size_t)row0 * HF + col] =
                        __floats2half2_rn(acc[nt][0], acc[nt][1]);
                if (row1 < N_NODES)
                    *(__half2*)&Hr[(size_t)row1 * HF + col] =
                        __floats2half2_rn(acc[nt][2], acc[nt][3]);
            }
        }
    }
}

// ---------------------------------------------------------------------------
// Edge scatter: 16 lanes per edge (2 edges per warp); lane l reads 8 halves
// (16B).  out[row % N] += value * H[row / N][col]
// ---------------------------------------------------------------------------
__global__ __launch_bounds__(256) void rgcn_scatter(
    const int*   __restrict__ rows,
    const int*   __restrict__ cols,
    const float* __restrict__ vals,
    float*       __restrict__ out,
    int nnz)
{
    int t = blockIdx.x * 256 + threadIdx.x;
    int e = t >> 4;
    int l = t & 15;
    if (e >= nnz) return;

    int row = __ldg(rows + e);
    int c   = __ldg(cols + e);
    float v = __ldg(vals + e);
    int r = row / N_NODES;
    int n = row - r * N_NODES;

    const uint4* src = (const uint4*)(g_Hh + ((size_t)r * N_NODES + c) * HF);
    uint4 p = __ldg(src + l);                 // 8 halves

    __half2* hp = (__half2*)&p;
    float2 f0 = __half22float2(hp[0]);
    float2 f1 = __half22float2(hp[1]);
    float2 f2 = __half22float2(hp[2]);
    float2 f3 = __half22float2(hp[3]);

    float* dst = out + (size_t)n * HF + l * 8;
    asm volatile("red.global.add.v4.f32 [%0], {%1,%2,%3,%4};"
                 :: "l"(dst), "f"(v * f0.x), "f"(v * f0.y),
                    "f"(v * f1.x), "f"(v * f1.y) : "memory");
    asm volatile("red.global.add.v4.f32 [%0], {%1,%2,%3,%4};"
                 :: "l"(dst + 4), "f"(v * f2.x), "f"(v * f2.y),
                    "f"(v * f3.x), "f"(v * f3.y) : "memory");
}

// ---------------------------------------------------------------------------
__global__ void relu_kernel(float4* out, int n4) {
    int i = blockIdx.x * blockDim.x + threadIdx.x;
    if (i < n4) {
        float4 v = out[i];
        v.x = fmaxf(v.x, 0.f); v.y = fmaxf(v.y, 0.f);
        v.z = fmaxf(v.z, 0.f); v.w = fmaxf(v.w, 0.f);
        out[i] = v;
    }
}

// ---------------------------------------------------------------------------
extern "C" void kernel_launch(void* const* d_in, const int* in_sizes, int n_in,
                              void* d_out, int out_size) {
    const float* nodes   = (const float*)d_in[0];
    const int*   indices = (const int*)d_in[1];   // int32 (jax x64 disabled)
    const float* vals    = (const float*)d_in[2];
    const float* weights = (const float*)d_in[3];
    float* out = (float*)d_out;

    const int nnz = in_sizes[2];            // 1,600,000
    const int n4  = N_NODES * HF / 4;       // 3,200,000 float4s in out

    zero_kernel<<<(n4 + 255) / 256, 256>>>((float4*)out, n4);

    cudaFuncSetAttribute(rgcn_gemm, cudaFuncAttributeMaxDynamicSharedMemorySize,
                         GEMM_SMEM);
    rgcn_gemm<<<(N_NODES + 127) / 128, 256, GEMM_SMEM>>>(nodes, weights);

    rgcn_scatter<<<((size_t)nnz * 16 + 255) / 256, 256>>>(
        indices, indices + nnz, vals, out, nnz);

    relu_kernel<<<(n4 + 255) / 256, 256>>>((float4*)out, n4);
}

// round 5
// speedup vs baseline: 1.8792x; 1.1986x over previous
#include <cuda_runtime.h>
#include <cuda_fp16.h>
#include <cstdint>
#include <cstddef>

#define N_NODES 100000
#define R_REL   8
#define HF      128

// 8 * 100000 * 128 halves = 204.8 MB scratch for H[r][node][hto] (fp16)
__device__ __half g_Hh[(size_t)R_REL * N_NODES * HF];

// ---------------------------------------------------------------------------
__global__ void zero_kernel(float4* out, int n4) {
    int i = blockIdx.x * blockDim.x + threadIdx.x;
    if (i < n4) out[i] = make_float4(0.f, 0.f, 0.f, 0.f);
}

// ---------------------------------------------------------------------------
// GEMM: H[r] = nodes @ W[r]^T  (fp16 mma.sync m16n8k16, fp32 accumulate).
// Block tile 128x128, warp tile 128x16 (R2 structure). B fragments in regs
// per relation; A re-read from conflict-free padded smem. 2 CTAs/SM.
// ---------------------------------------------------------------------------
#define LDAH 136   // halves per smem row (stride mod 32 words = 4 -> conflict-free)
#define GEMM_SMEM (2 * 128 * LDAH * 2)   // As + Bs in halves

__global__ __launch_bounds__(256, 2) void rgcn_gemm(
    const float* __restrict__ nodes, const float* __restrict__ weights)
{
    extern __shared__ __half smem[];
    __half* As = smem;               // [128][LDAH]  (row m, col k)
    __half* Bs = smem + 128 * LDAH;  // [128][LDAH]  Bs[n][k] = W[r][n][k]

    const int tid  = threadIdx.x;
    const int warp = tid >> 5;
    const int lane = tid & 31;
    const int g    = lane >> 2;   // groupID (0..7)
    const int tg   = lane & 3;    // thread-in-group (0..3)
    const int m0   = blockIdx.x * 128;
    const int nbase = warp * 16;  // each warp owns 16 output columns

    // ---- load A tile (zero-pad rows >= N_NODES), convert to fp16 ----
    {
        const float4* src = (const float4*)nodes;
        #pragma unroll
        for (int i = tid; i < 128 * 32; i += 256) {
            int row = i >> 5, c4 = i & 31;
            float4 v = make_float4(0.f, 0.f, 0.f, 0.f);
            if (m0 + row < N_NODES) v = src[(size_t)(m0 + row) * 32 + c4];
            __half2 h0 = __floats2half2_rn(v.x, v.y);
            __half2 h1 = __floats2half2_rn(v.z, v.w);
            uint2 pk = make_uint2(*(uint32_t*)&h0, *(uint32_t*)&h1);
            *(uint2*)&As[row * LDAH + c4 * 4] = pk;
        }
    }

    for (int r = 0; r < R_REL; r++) {
        __syncthreads();   // prev iter's B-reg loads done (and A fill on iter 0)
        // ---- stage W[r] into smem: Bs[n][k], fp16 ----
        {
            const float4* src = (const float4*)(weights + (size_t)r * HF * HF);
            #pragma unroll
            for (int i = tid; i < 128 * 32; i += 256) {
                int n = i >> 5, k4 = i & 31;
                float4 v = src[n * 32 + k4];
                __half2 h0 = __floats2half2_rn(v.x, v.y);
                __half2 h1 = __floats2half2_rn(v.z, v.w);
                uint2 pk = make_uint2(*(uint32_t*)&h0, *(uint32_t*)&h1);
                *(uint2*)&Bs[n * LDAH + k4 * 4] = pk;
            }
        }
        __syncthreads();

        // ---- B fragments for this warp's 16 columns, all K, held in regs ----
        // m16n8k16 B frag: b0 = {B[k=2tg][n=g], B[2tg+1][g]}, b1 = k+8 pair
        uint32_t breg[8][2][2];
        #pragma unroll
        for (int kk = 0; kk < 8; kk++) {
            #pragma unroll
            for (int nt = 0; nt < 2; nt++) {
                int n = nbase + nt * 8 + g;
                breg[kk][nt][0] = *(uint32_t*)&Bs[n * LDAH + kk * 16 + 2 * tg];
                breg[kk][nt][1] = *(uint32_t*)&Bs[n * LDAH + kk * 16 + 2 * tg + 8];
            }
        }

        __half* Hr = g_Hh + (size_t)r * N_NODES * HF;
        #pragma unroll 1
        for (int msub = 0; msub < 8; msub++) {
            float acc[2][4] = {};
            const int mrow = msub * 16;
            #pragma unroll
            for (int kk = 0; kk < 8; kk++) {
                uint32_t a0 = *(uint32_t*)&As[(mrow + g)     * LDAH + kk * 16 + 2 * tg];
                uint32_t a1 = *(uint32_t*)&As[(mrow + g + 8) * LDAH + kk * 16 + 2 * tg];
                uint32_t a2 = *(uint32_t*)&As[(mrow + g)     * LDAH + kk * 16 + 2 * tg + 8];
                uint32_t a3 = *(uint32_t*)&As[(mrow + g + 8) * LDAH + kk * 16 + 2 * tg + 8];
                #pragma unroll
                for (int nt = 0; nt < 2; nt++) {
                    asm volatile(
                        "mma.sync.aligned.m16n8k16.row.col.f32.f16.f16.f32 "
                        "{%0,%1,%2,%3}, {%4,%5,%6,%7}, {%8,%9}, {%0,%1,%2,%3};"
                        : "+f"(acc[nt][0]), "+f"(acc[nt][1]),
                          "+f"(acc[nt][2]), "+f"(acc[nt][3])
                        : "r"(a0), "r"(a1), "r"(a2), "r"(a3),
                          "r"(breg[kk][nt][0]), "r"(breg[kk][nt][1]));
                }
            }
            const int row0 = m0 + mrow + g;
            const int row1 = row0 + 8;
            #pragma unroll
            for (int nt = 0; nt < 2; nt++) {
                int col = nbase + nt * 8 + 2 * tg;
                if (row0 < N_NODES)
                    *(__half2*)&Hr[(size_t)row0 * HF + col] =
                        __floats2half2_rn(acc[nt][0], acc[nt][1]);
                if (row1 < N_NODES)
                    *(__half2*)&Hr[(size_t)row1 * HF + col] =
                        __floats2half2_rn(acc[nt][2], acc[nt][3]);
            }
        }
    }
}

// ---------------------------------------------------------------------------
// Edge scatter: 16 lanes per edge (2 edges per warp); lane l reads 8 halves
// (16B).  out[row % N] += value * H[row / N][col]
// ---------------------------------------------------------------------------
__global__ __launch_bounds__(256) void rgcn_scatter(
    const int*   __restrict__ rows,
    const int*   __restrict__ cols,
    const float* __restrict__ vals,
    float*       __restrict__ out,
    int nnz)
{
    int t = blockIdx.x * 256 + threadIdx.x;
    int e = t >> 4;
    int l = t & 15;
    if (e >= nnz) return;

    int row = __ldg(rows + e);
    int c   = __ldg(cols + e);
    float v = __ldg(vals + e);
    int r = row / N_NODES;
    int n = row - r * N_NODES;

    const uint4* src = (const uint4*)(g_Hh + ((size_t)r * N_NODES + c) * HF);
    uint4 p = __ldg(src + l);                 // 8 halves

    __half2* hp = (__half2*)&p;
    float2 f0 = __half22float2(hp[0]);
    float2 f1 = __half22float2(hp[1]);
    float2 f2 = __half22float2(hp[2]);
    float2 f3 = __half22float2(hp[3]);

    float* dst = out + (size_t)n * HF + l * 8;
    asm volatile("red.global.add.v4.f32 [%0], {%1,%2,%3,%4};"
                 :: "l"(dst), "f"(v * f0.x), "f"(v * f0.y),
                    "f"(v * f1.x), "f"(v * f1.y) : "memory");
    asm volatile("red.global.add.v4.f32 [%0], {%1,%2,%3,%4};"
                 :: "l"(dst + 4), "f"(v * f2.x), "f"(v * f2.y),
                    "f"(v * f3.x), "f"(v * f3.y) : "memory");
}

// ---------------------------------------------------------------------------
__global__ void relu_kernel(float4* out, int n4) {
    int i = blockIdx.x * blockDim.x + threadIdx.x;
    if (i < n4) {
        float4 v = out[i];
        v.x = fmaxf(v.x, 0.f); v.y = fmaxf(v.y, 0.f);
        v.z = fmaxf(v.z, 0.f); v.w = fmaxf(v.w, 0.f);
        out[i] = v;
    }
}

// ---------------------------------------------------------------------------
extern "C" void kernel_launch(void* const* d_in, const int* in_sizes, int n_in,
                              void* d_out, int out_size) {
    const float* nodes   = (const float*)d_in[0];
    const int*   indices = (const int*)d_in[1];   // int32 (jax x64 disabled)
    const float* vals    = (const float*)d_in[2];
    const float* weights = (const float*)d_in[3];
    float* out = (float*)d_out;

    const int nnz = in_sizes[2];            // 1,600,000
    const int n4  = N_NODES * HF / 4;       // 3,200,000 float4s in out

    zero_kernel<<<(n4 + 255) / 256, 256>>>((float4*)out, n4);

    cudaFuncSetAttribute(rgcn_gemm, cudaFuncAttributeMaxDynamicSharedMemorySize,
                         GEMM_SMEM);
    rgcn_gemm<<<(N_NODES + 127) / 128, 256, GEMM_SMEM>>>(nodes, weights);

    rgcn_scatter<<<((size_t)nnz * 16 + 255) / 256, 256>>>(
        indices, indices + nnz, vals, out, nnz);

    relu_kernel<<<(n4 + 255) / 256, 256>>>((float4*)out, n4);
}

// round 9
// speedup vs baseline: 2.6631x; 1.4171x over previous
#include <cuda_runtime.h>
#include <cuda_fp16.h>
#include <cstdint>
#include <cstddef>

#define N_NODES 100000
#define R_REL   8
#define HF      128
#define NNZ_MAX 1600000

// 204.8 MB scratch for H[r][node][hto] (fp16)
__device__ __half g_Hh[(size_t)R_REL * N_NODES * HF];

// CSR-by-destination scratch
__device__ int   g_cnt[N_NODES];
__device__ int   g_cur[N_NODES];
__device__ int   g_off[N_NODES];
__device__ int   g_bsum[128];
__device__ int   g_eidx[NNZ_MAX];   // H row index (r*N + c) per edge, dest-sorted
__device__ float g_ev[NNZ_MAX];     // edge value, dest-sorted

// ---------------------------------------------------------------------------
// GEMM: H[r] = nodes @ W[r]^T  (fp16 mma.sync m16n8k16, fp32 accumulate).
// Block tile 128x128, warp tile 128x16. 2 CTAs/SM.
// ---------------------------------------------------------------------------
#define LDAH 136
#define GEMM_SMEM (2 * 128 * LDAH * 2)

__global__ __launch_bounds__(256, 2) void rgcn_gemm(
    const float* __restrict__ nodes, const float* __restrict__ weights)
{
    extern __shared__ __half smem[];
    __half* As = smem;               // [128][LDAH]
    __half* Bs = smem + 128 * LDAH;  // [128][LDAH]  Bs[n][k]

    const int tid  = threadIdx.x;
    const int warp = tid >> 5;
    const int lane = tid & 31;
    const int g    = lane >> 2;
    const int tg   = lane & 3;
    const int m0   = blockIdx.x * 128;
    const int nbase = warp * 16;

    {
        const float4* src = (const float4*)nodes;
        #pragma unroll
        for (int i = tid; i < 128 * 32; i += 256) {
            int row = i >> 5, c4 = i & 31;
            float4 v = make_float4(0.f, 0.f, 0.f, 0.f);
            if (m0 + row < N_NODES) v = src[(size_t)(m0 + row) * 32 + c4];
            __half2 h0 = __floats2half2_rn(v.x, v.y);
            __half2 h1 = __floats2half2_rn(v.z, v.w);
            uint2 pk = make_uint2(*(uint32_t*)&h0, *(uint32_t*)&h1);
            *(uint2*)&As[row * LDAH + c4 * 4] = pk;
        }
    }

    for (int r = 0; r < R_REL; r++) {
        __syncthreads();
        {
            const float4* src = (const float4*)(weights + (size_t)r * HF * HF);
            #pragma unroll
            for (int i = tid; i < 128 * 32; i += 256) {
                int n = i >> 5, k4 = i & 31;
                float4 v = src[n * 32 + k4];
                __half2 h0 = __floats2half2_rn(v.x, v.y);
                __half2 h1 = __floats2half2_rn(v.z, v.w);
                uint2 pk = make_uint2(*(uint32_t*)&h0, *(uint32_t*)&h1);
                *(uint2*)&Bs[n * LDAH + k4 * 4] = pk;
            }
        }
        __syncthreads();

        uint32_t breg[8][2][2];
        #pragma unroll
        for (int kk = 0; kk < 8; kk++) {
            #pragma unroll
            for (int nt = 0; nt < 2; nt++) {
                int n = nbase + nt * 8 + g;
                breg[kk][nt][0] = *(uint32_t*)&Bs[n * LDAH + kk * 16 + 2 * tg];
                breg[kk][nt][1] = *(uint32_t*)&Bs[n * LDAH + kk * 16 + 2 * tg + 8];
            }
        }

        __half* Hr = g_Hh + (size_t)r * N_NODES * HF;
        #pragma unroll 1
        for (int msub = 0; msub < 8; msub++) {
            float acc[2][4] = {};
            const int mrow = msub * 16;
            #pragma unroll
            for (int kk = 0; kk < 8; kk++) {
                uint32_t a0 = *(uint32_t*)&As[(mrow + g)     * LDAH + kk * 16 + 2 * tg];
                uint32_t a1 = *(uint32_t*)&As[(mrow + g + 8) * LDAH + kk * 16 + 2 * tg];
                uint32_t a2 = *(uint32_t*)&As[(mrow + g)     * LDAH + kk * 16 + 2 * tg + 8];
                uint32_t a3 = *(uint32_t*)&As[(mrow + g + 8) * LDAH + kk * 16 + 2 * tg + 8];
                #pragma unroll
                for (int nt = 0; nt < 2; nt++) {
                    asm volatile(
                        "mma.sync.aligned.m16n8k16.row.col.f32.f16.f16.f32 "
                        "{%0,%1,%2,%3}, {%4,%5,%6,%7}, {%8,%9}, {%0,%1,%2,%3};"
                        : "+f"(acc[nt][0]), "+f"(acc[nt][1]),
                          "+f"(acc[nt][2]), "+f"(acc[nt][3])
                        : "r"(a0), "r"(a1), "r"(a2), "r"(a3),
                          "r"(breg[kk][nt][0]), "r"(breg[kk][nt][1]));
                }
            }
            const int row0 = m0 + mrow + g;
            const int row1 = row0 + 8;
            #pragma unroll
            for (int nt = 0; nt < 2; nt++) {
                int col = nbase + nt * 8 + 2 * tg;
                if (row0 < N_NODES)
                    *(__half2*)&Hr[(size_t)row0 * HF + col] =
                        __floats2half2_rn(acc[nt][0], acc[nt][1]);
                if (row1 < N_NODES)
                    *(__half2*)&Hr[(size_t)row1 * HF + col] =
                        __floats2half2_rn(acc[nt][2], acc[nt][3]);
            }
        }
    }
}

// ---------------------------------------------------------------------------
// CSR build: zero counters -> histogram -> exclusive scan -> permute edges
// ---------------------------------------------------------------------------
__global__ void zero_counters() {
    int i = blockIdx.x * blockDim.x + threadIdx.x;
    if (i < N_NODES) { g_cnt[i] = 0; g_cur[i] = 0; }
}

__global__ void hist_kernel(const int* __restrict__ rows, int nnz) {
    int e = blockIdx.x * blockDim.x + threadIdx.x;
    if (e >= nnz) return;
    int row = __ldg(rows + e);
    int n = row % N_NODES;
    atomicAdd(&g_cnt[n], 1);
}

#define SCAN_T 1024
#define SCAN_NB ((N_NODES + SCAN_T - 1) / SCAN_T)   // 98

__global__ void scan_partial() {
    __shared__ int s[SCAN_T];
    int i = blockIdx.x * SCAN_T + threadIdx.x;
    int v = (i < N_NODES) ? g_cnt[i] : 0;
    s[threadIdx.x] = v; __syncthreads();
    #pragma unroll
    for (int d = 1; d < SCAN_T; d <<= 1) {
        int t = (threadIdx.x >= d) ? s[threadIdx.x - d] : 0;
        __syncthreads();
        s[threadIdx.x] += t;
        __syncthreads();
    }
    if (i < N_NODES) g_off[i] = s[threadIdx.x] - v;   // exclusive
    if (threadIdx.x == SCAN_T - 1) g_bsum[blockIdx.x] = s[SCAN_T - 1];
}

__global__ void scan_bsum() {   // single block of 128 (>= SCAN_NB)
    __shared__ int s[128];
    int v = (threadIdx.x < SCAN_NB) ? g_bsum[threadIdx.x] : 0;
    s[threadIdx.x] = v; __syncthreads();
    #pragma unroll
    for (int d = 1; d < 128; d <<= 1) {
        int t = (threadIdx.x >= d) ? s[threadIdx.x - d] : 0;
        __syncthreads();
        s[threadIdx.x] += t;
        __syncthreads();
    }
    if (threadIdx.x < SCAN_NB) g_bsum[threadIdx.x] = s[threadIdx.x] - v;  // exclusive
}

__global__ void scan_add() {
    int i = blockIdx.x * SCAN_T + threadIdx.x;
    if (i < N_NODES) g_off[i] += g_bsum[blockIdx.x];
}

__global__ void fill_kernel(const int* __restrict__ rows,
                            const int* __restrict__ cols,
                            const float* __restrict__ vals, int nnz) {
    int e = blockIdx.x * blockDim.x + threadIdx.x;
    if (e >= nnz) return;
    int row = __ldg(rows + e);
    int c   = __ldg(cols + e);
    float v = __ldg(vals + e);
    int r = row / N_NODES;
    int n = row - r * N_NODES;
    int pos = g_off[n] + atomicAdd(&g_cur[n], 1);
    g_eidx[pos] = r * N_NODES + c;
    g_ev[pos]   = v;
}

// ---------------------------------------------------------------------------
// Node gather: one warp per destination node. Lane l owns output cols
// [4l, 4l+4). Accumulate in registers, ReLU, single float4 store.
// ---------------------------------------------------------------------------
__global__ __launch_bounds__(256) void node_gather(float* __restrict__ out) {
    int n    = (blockIdx.x * 256 + threadIdx.x) >> 5;
    int lane = threadIdx.x & 31;
    if (n >= N_NODES) return;

    int start = g_off[n];
    int deg   = g_cnt[n];
    int end   = start + deg;

    float4 acc = make_float4(0.f, 0.f, 0.f, 0.f);

    int j = start;
    for (; j + 1 < end; j += 2) {
        int   h0 = __ldg(&g_eidx[j]);
        int   h1 = __ldg(&g_eidx[j + 1]);
        float v0 = __ldg(&g_ev[j]);
        float v1 = __ldg(&g_ev[j + 1]);
        uint2 p0 = __ldg((const uint2*)&g_Hh[(size_t)h0 * HF + lane * 4]);
        uint2 p1 = __ldg((const uint2*)&g_Hh[(size_t)h1 * HF + lane * 4]);
        float2 a0 = __half22float2(*(__half2*)&p0.x);
        float2 a1 = __half22float2(*(__half2*)&p0.y);
        float2 b0 = __half22float2(*(__half2*)&p1.x);
        float2 b1 = __half22float2(*(__half2*)&p1.y);
        acc.x += v0 * a0.x + v1 * b0.x;
        acc.y += v0 * a0.y + v1 * b0.y;
        acc.z += v0 * a1.x + v1 * b1.x;
        acc.w += v0 * a1.y + v1 * b1.y;
    }
    if (j < end) {
        int   h0 = __ldg(&g_eidx[j]);
        float v0 = __ldg(&g_ev[j]);
        uint2 p0 = __ldg((const uint2*)&g_Hh[(size_t)h0 * HF + lane * 4]);
        float2 a0 = __half22float2(*(__half2*)&p0.x);
        float2 a1 = __half22float2(*(__half2*)&p0.y);
        acc.x += v0 * a0.x; acc.y += v0 * a0.y;
        acc.z += v0 * a1.x; acc.w += v0 * a1.y;
    }

    acc.x = fmaxf(acc.x, 0.f); acc.y = fmaxf(acc.y, 0.f);
    acc.z = fmaxf(acc.z, 0.f); acc.w = fmaxf(acc.w, 0.f);
    *(float4*)&out[(size_t)n * HF + lane * 4] = acc;
}

// ---------------------------------------------------------------------------
extern "C" void kernel_launch(void* const* d_in, const int* in_sizes, int n_in,
                              void* d_out, int out_size) {
    const float* nodes   = (const float*)d_in[0];
    const int*   indices = (const int*)d_in[1];   // int32 (jax x64 disabled)
    const float* vals    = (const float*)d_in[2];
    const float* weights = (const float*)d_in[3];
    float* out = (float*)d_out;

    const int nnz = in_sizes[2];   // 1,600,000

    // CSR build (independent of GEMM)
    zero_counters<<<(N_NODES + 255) / 256, 256>>>();
    hist_kernel<<<(nnz + 255) / 256, 256>>>(indices, nnz);
    scan_partial<<<SCAN_NB, SCAN_T>>>();
    scan_bsum<<<1, 128>>>();
    scan_add<<<SCAN_NB, SCAN_T>>>();
    fill_kernel<<<(nnz + 255) / 256, 256>>>(indices, indices + nnz, vals, nnz);

    // Dense transform
    cudaFuncSetAttribute(rgcn_gemm, cudaFuncAttributeMaxDynamicSharedMemorySize,
                         GEMM_SMEM);
    rgcn_gemm<<<(N_NODES + 127) / 128, 256, GEMM_SMEM>>>(nodes, weights);

    // Gather + ReLU + store (writes every output row; no zero/relu kernels)
    node_gather<<<(N_NODES * 32 + 255) / 256, 256>>>(out);
}

// round 10
// speedup vs baseline: 2.8415x; 1.0670x over previous
#include <cuda_runtime.h>
#include <cuda_fp16.h>
#include <cstdint>
#include <cstddef>

#define N_NODES 100000
#define R_REL   8
#define HF      128
#define NNZ_MAX 1600000

// 204.8 MB scratch for H[r][node][hto] (fp16)
__device__ __half g_Hh[(size_t)R_REL * N_NODES * HF];

// CSR-by-destination scratch
__device__ int   g_cnt[N_NODES];
__device__ int   g_cur[N_NODES];
__device__ int   g_off[N_NODES];
__device__ int   g_bsum[128];
__device__ int   g_eidx[NNZ_MAX];   // H row index (r*N + c) per edge, dest-sorted
__device__ float g_ev[NNZ_MAX];     // edge value, dest-sorted

// ---------------------------------------------------------------------------
// GEMM: H[r] = nodes @ W[r]^T  (fp16 mma.sync m16n8k16, fp32 accumulate).
// Block tile 128x128, warp tile 128x16. 2 CTAs/SM.
// ---------------------------------------------------------------------------
#define LDAH 136
#define GEMM_SMEM (2 * 128 * LDAH * 2)

__global__ __launch_bounds__(256, 2) void rgcn_gemm(
    const float* __restrict__ nodes, const float* __restrict__ weights)
{
    extern __shared__ __half smem[];
    __half* As = smem;               // [128][LDAH]
    __half* Bs = smem + 128 * LDAH;  // [128][LDAH]  Bs[n][k]

    const int tid  = threadIdx.x;
    const int warp = tid >> 5;
    const int lane = tid & 31;
    const int g    = lane >> 2;
    const int tg   = lane & 3;
    const int m0   = blockIdx.x * 128;
    const int nbase = warp * 16;

    {
        const float4* src = (const float4*)nodes;
        #pragma unroll
        for (int i = tid; i < 128 * 32; i += 256) {
            int row = i >> 5, c4 = i & 31;
            float4 v = make_float4(0.f, 0.f, 0.f, 0.f);
            if (m0 + row < N_NODES) v = src[(size_t)(m0 + row) * 32 + c4];
            __half2 h0 = __floats2half2_rn(v.x, v.y);
            __half2 h1 = __floats2half2_rn(v.z, v.w);
            uint2 pk = make_uint2(*(uint32_t*)&h0, *(uint32_t*)&h1);
            *(uint2*)&As[row * LDAH + c4 * 4] = pk;
        }
    }

    for (int r = 0; r < R_REL; r++) {
        __syncthreads();
        {
            const float4* src = (const float4*)(weights + (size_t)r * HF * HF);
            #pragma unroll
            for (int i = tid; i < 128 * 32; i += 256) {
                int n = i >> 5, k4 = i & 31;
                float4 v = src[n * 32 + k4];
                __half2 h0 = __floats2half2_rn(v.x, v.y);
                __half2 h1 = __floats2half2_rn(v.z, v.w);
                uint2 pk = make_uint2(*(uint32_t*)&h0, *(uint32_t*)&h1);
                *(uint2*)&Bs[n * LDAH + k4 * 4] = pk;
            }
        }
        __syncthreads();

        uint32_t breg[8][2][2];
        #pragma unroll
        for (int kk = 0; kk < 8; kk++) {
            #pragma unroll
            for (int nt = 0; nt < 2; nt++) {
                int n = nbase + nt * 8 + g;
                breg[kk][nt][0] = *(uint32_t*)&Bs[n * LDAH + kk * 16 + 2 * tg];
                breg[kk][nt][1] = *(uint32_t*)&Bs[n * LDAH + kk * 16 + 2 * tg + 8];
            }
        }

        __half* Hr = g_Hh + (size_t)r * N_NODES * HF;
        #pragma unroll 1
        for (int msub = 0; msub < 8; msub++) {
            float acc[2][4] = {};
            const int mrow = msub * 16;
            #pragma unroll
            for (int kk = 0; kk < 8; kk++) {
                uint32_t a0 = *(uint32_t*)&As[(mrow + g)     * LDAH + kk * 16 + 2 * tg];
                uint32_t a1 = *(uint32_t*)&As[(mrow + g + 8) * LDAH + kk * 16 + 2 * tg];
                uint32_t a2 = *(uint32_t*)&As[(mrow + g)     * LDAH + kk * 16 + 2 * tg + 8];
                uint32_t a3 = *(uint32_t*)&As[(mrow + g + 8) * LDAH + kk * 16 + 2 * tg + 8];
                #pragma unroll
                for (int nt = 0; nt < 2; nt++) {
                    asm volatile(
                        "mma.sync.aligned.m16n8k16.row.col.f32.f16.f16.f32 "
                        "{%0,%1,%2,%3}, {%4,%5,%6,%7}, {%8,%9}, {%0,%1,%2,%3};"
                        : "+f"(acc[nt][0]), "+f"(acc[nt][1]),
                          "+f"(acc[nt][2]), "+f"(acc[nt][3])
                        : "r"(a0), "r"(a1), "r"(a2), "r"(a3),
                          "r"(breg[kk][nt][0]), "r"(breg[kk][nt][1]));
                }
            }
            const int row0 = m0 + mrow + g;
            const int row1 = row0 + 8;
            #pragma unroll
            for (int nt = 0; nt < 2; nt++) {
                int col = nbase + nt * 8 + 2 * tg;
                if (row0 < N_NODES)
                    *(__half2*)&Hr[(size_t)row0 * HF + col] =
                        __floats2half2_rn(acc[nt][0], acc[nt][1]);
                if (row1 < N_NODES)
                    *(__half2*)&Hr[(size_t)row1 * HF + col] =
                        __floats2half2_rn(acc[nt][2], acc[nt][3]);
            }
        }
    }
}

// ---------------------------------------------------------------------------
// CSR build: zero counters -> histogram -> exclusive scan -> permute edges
// ---------------------------------------------------------------------------
__global__ void zero_counters() {
    int i = blockIdx.x * blockDim.x + threadIdx.x;
    if (i < N_NODES) { g_cnt[i] = 0; g_cur[i] = 0; }
}

__global__ void hist_kernel(const int* __restrict__ rows, int nnz) {
    int e = blockIdx.x * blockDim.x + threadIdx.x;
    if (e >= nnz) return;
    int row = __ldg(rows + e);
    int n = row % N_NODES;
    atomicAdd(&g_cnt[n], 1);
}

#define SCAN_T 1024
#define SCAN_NB ((N_NODES + SCAN_T - 1) / SCAN_T)   // 98

__global__ void scan_partial() {
    __shared__ int s[SCAN_T];
    int i = blockIdx.x * SCAN_T + threadIdx.x;
    int v = (i < N_NODES) ? g_cnt[i] : 0;
    s[threadIdx.x] = v; __syncthreads();
    #pragma unroll
    for (int d = 1; d < SCAN_T; d <<= 1) {
        int t = (threadIdx.x >= d) ? s[threadIdx.x - d] : 0;
        __syncthreads();
        s[threadIdx.x] += t;
        __syncthreads();
    }
    if (i < N_NODES) g_off[i] = s[threadIdx.x] - v;   // exclusive
    if (threadIdx.x == SCAN_T - 1) g_bsum[blockIdx.x] = s[SCAN_T - 1];
}

__global__ void scan_bsum() {   // single block of 128 (>= SCAN_NB)
    __shared__ int s[128];
    int v = (threadIdx.x < SCAN_NB) ? g_bsum[threadIdx.x] : 0;
    s[threadIdx.x] = v; __syncthreads();
    #pragma unroll
    for (int d = 1; d < 128; d <<= 1) {
        int t = (threadIdx.x >= d) ? s[threadIdx.x - d] : 0;
        __syncthreads();
        s[threadIdx.x] += t;
        __syncthreads();
    }
    if (threadIdx.x < SCAN_NB) g_bsum[threadIdx.x] = s[threadIdx.x] - v;  // exclusive
}

__global__ void scan_add() {
    int i = blockIdx.x * SCAN_T + threadIdx.x;
    if (i < N_NODES) g_off[i] += g_bsum[blockIdx.x];
}

__global__ void fill_kernel(const int* __restrict__ rows,
                            const int* __restrict__ cols,
                            const float* __restrict__ vals, int nnz) {
    int e = blockIdx.x * blockDim.x + threadIdx.x;
    if (e >= nnz) return;
    int row = __ldg(rows + e);
    int c   = __ldg(cols + e);
    float v = __ldg(vals + e);
    int r = row / N_NODES;
    int n = row - r * N_NODES;
    int pos = g_off[n] + atomicAdd(&g_cur[n], 1);
    g_eidx[pos] = r * N_NODES + c;
    g_ev[pos]   = v;
}

// ---------------------------------------------------------------------------
// Node gather: one warp per destination node. Lane l owns output cols
// [4l, 4l+4). 4-edge unrolled accumulate in registers, ReLU, float4 store.
// ---------------------------------------------------------------------------
__global__ __launch_bounds__(256) void node_gather(float* __restrict__ out) {
    int n    = (blockIdx.x * 256 + threadIdx.x) >> 5;
    int lane = threadIdx.x & 31;
    if (n >= N_NODES) return;

    int start = g_off[n];
    int deg   = g_cnt[n];
    int end   = start + deg;

    float4 acc = make_float4(0.f, 0.f, 0.f, 0.f);

    int j = start;
    for (; j + 3 < end; j += 4) {
        int   h0 = __ldg(&g_eidx[j]);
        int   h1 = __ldg(&g_eidx[j + 1]);
        int   h2 = __ldg(&g_eidx[j + 2]);
        int   h3 = __ldg(&g_eidx[j + 3]);
        float v0 = __ldg(&g_ev[j]);
        float v1 = __ldg(&g_ev[j + 1]);
        float v2 = __ldg(&g_ev[j + 2]);
        float v3 = __ldg(&g_ev[j + 3]);
        uint2 p0 = __ldg((const uint2*)&g_Hh[(size_t)h0 * HF + lane * 4]);
        uint2 p1 = __ldg((const uint2*)&g_Hh[(size_t)h1 * HF + lane * 4]);
        uint2 p2 = __ldg((const uint2*)&g_Hh[(size_t)h2 * HF + lane * 4]);
        uint2 p3 = __ldg((const uint2*)&g_Hh[(size_t)h3 * HF + lane * 4]);
        float2 a0 = __half22float2(*(__half2*)&p0.x);
        float2 a1 = __half22float2(*(__half2*)&p0.y);
        float2 b0 = __half22float2(*(__half2*)&p1.x);
        float2 b1 = __half22float2(*(__half2*)&p1.y);
        float2 c0 = __half22float2(*(__half2*)&p2.x);
        float2 c1 = __half22float2(*(__half2*)&p2.y);
        float2 d0 = __half22float2(*(__half2*)&p3.x);
        float2 d1 = __half22float2(*(__half2*)&p3.y);
        acc.x += v0 * a0.x + v1 * b0.x + v2 * c0.x + v3 * d0.x;
        acc.y += v0 * a0.y + v1 * b0.y + v2 * c0.y + v3 * d0.y;
        acc.z += v0 * a1.x + v1 * b1.x + v2 * c1.x + v3 * d1.x;
        acc.w += v0 * a1.y + v1 * b1.y + v2 * c1.y + v3 * d1.y;
    }
    for (; j < end; j++) {
        int   h0 = __ldg(&g_eidx[j]);
        float v0 = __ldg(&g_ev[j]);
        uint2 p0 = __ldg((const uint2*)&g_Hh[(size_t)h0 * HF + lane * 4]);
        float2 a0 = __half22float2(*(__half2*)&p0.x);
        float2 a1 = __half22float2(*(__half2*)&p0.y);
        acc.x += v0 * a0.x; acc.y += v0 * a0.y;
        acc.z += v0 * a1.x; acc.w += v0 * a1.y;
    }

    acc.x = fmaxf(acc.x, 0.f); acc.y = fmaxf(acc.y, 0.f);
    acc.z = fmaxf(acc.z, 0.f); acc.w = fmaxf(acc.w, 0.f);
    *(float4*)&out[(size_t)n * HF + lane * 4] = acc;
}

// ---------------------------------------------------------------------------
extern "C" void kernel_launch(void* const* d_in, const int* in_sizes, int n_in,
                              void* d_out, int out_size) {
    const float* nodes   = (const float*)d_in[0];
    const int*   indices = (const int*)d_in[1];   // int32 (jax x64 disabled)
    const float* vals    = (const float*)d_in[2];
    const float* weights = (const float*)d_in[3];
    float* out = (float*)d_out;

    const int nnz = in_sizes[2];   // 1,600,000

    // Side stream + fork/join events, created once on the first (correctness)
    // call. No device memory is involved; the captured work is identical on
    // every call.
    static cudaStream_t s_csr = nullptr;
    static cudaEvent_t  ev_fork = nullptr, ev_join = nullptr;
    if (!s_csr) {
        cudaStreamCreateWithFlags(&s_csr, cudaStreamNonBlocking);
        cudaEventCreateWithFlags(&ev_fork, cudaEventDisableTiming);
        cudaEventCreateWithFlags(&ev_join, cudaEventDisableTiming);
    }

    // ---- fork: CSR build chain runs concurrently with the GEMM ----
    cudaEventRecord(ev_fork, 0);
    cudaStreamWaitEvent(s_csr, ev_fork, 0);

    zero_counters<<<(N_NODES + 255) / 256, 256, 0, s_csr>>>();
    hist_kernel<<<(nnz + 255) / 256, 256, 0, s_csr>>>(indices, nnz);
    scan_partial<<<SCAN_NB, SCAN_T, 0, s_csr>>>();
    scan_bsum<<<1, 128, 0, s_csr>>>();
    scan_add<<<SCAN_NB, SCAN_T, 0, s_csr>>>();
    fill_kernel<<<(nnz + 255) / 256, 256, 0, s_csr>>>(
        indices, indices + nnz, vals, nnz);
    cudaEventRecord(ev_join, s_csr);

    // ---- dense transform on the main stream (overlaps CSR build) ----
    cudaFuncSetAttribute(rgcn_gemm, cudaFuncAttributeMaxDynamicSharedMemorySize,
                         GEMM_SMEM);
    rgcn_gemm<<<(N_NODES + 127) / 128, 256, GEMM_SMEM>>>(nodes, weights);

    // ---- join, then gather + ReLU + store ----
    cudaStreamWaitEvent(0, ev_join, 0);
    node_gather<<<(N_NODES * 32 + 255) / 256, 256>>>(out);
}